// round 6
// baseline (speedup 1.0000x reference)
#include <cuda_runtime.h>
#include <math.h>

#define T_SAMPLES 8388608
#define NFRAMES   16381
#define NBINS     84
#define FBINS     1025
#define FFTLEN    2048
#define HOP       512

// main kernel tiling
#define FT   64     // frames per block (32 lanes x 2 frames/thread)
#define KT   28     // bins per block (7 warps x 4 bins)
#define CH   128    // n-chunk staged in smem
#define XR   132    // x-chunk row stride (128 + 4 pad: %32==4 -> conflict-free LDS128)

#define SMEM_FLOATS (FT*XR + 2*KT*CH)
#define SMEM_BYTES  (SMEM_FLOATS * 4)

typedef unsigned long long ull;

// Combined CQT kernels: A = kr@wcos - ki@wsin, B = kr@wsin + ki@wcos
__device__ float g_A[NBINS * FFTLEN];
__device__ float g_B[NBINS * FFTLEN];

__device__ __forceinline__ ull ffma2(ull a, ull b, ull c) {
    ull d;
    asm("fma.rn.f32x2 %0, %1, %2, %3;" : "=l"(d) : "l"(a), "l"(b), "l"(c));
    return d;
}

__device__ __forceinline__ ull pack2(float lo, float hi) {
    ull r;
    asm("mov.b64 %0, {%1, %2};" : "=l"(r) : "f"(lo), "f"(hi));
    return r;
}

#define LDSV2(lo, hi, addr) \
    asm volatile("ld.shared.v2.u64 {%0, %1}, [%2];" : "=l"(lo), "=l"(hi) : "r"(addr))

__device__ __forceinline__ float hsum2(ull v) {
    union { ull u; float2 f; } c; c.u = v;
    return c.f.x + c.f.y;
}

// ---------------------------------------------------------------------------
// Precompute A,B [84,2048] = combine(kr,ki [84,1025] ; wcos,wsin [1025,2048])
// Packed f32x2: each thread owns one n-PAIR, 3 bins. Block = 4 k-slots x 64
// n-pairs (256 thr). kr/ki staged pre-splatted (incl. negated ki) in smem.
// Grid (16,7) = 112 blocks -> single balanced wave.
// ---------------------------------------------------------------------------
__global__ void __launch_bounds__(256) cqt_precomp(const float* __restrict__ wcos,
                                                   const float* __restrict__ wsin,
                                                   const float* __restrict__ kr,
                                                   const float* __restrict__ ki) {
    __shared__ ull s_r [12 * 64];   // {vr, vr}
    __shared__ ull s_in[12 * 64];   // {-vi,-vi}
    __shared__ ull s_ip[12 * 64];   // {vi, vi}
    const int tid = threadIdx.x;
    const int np  = blockIdx.x * 64 + (tid & 63);   // n-pair: n = 2*np, 2*np+1
    const int ks  = tid >> 6;                       // 0..3
    const int kb  = blockIdx.y * 12;                // 7 blocks -> 84 bins

    const ull* wc2 = (const ull*)wcos;
    const ull* ws2 = (const ull*)wsin;

    ull aA[3] = {0ULL, 0ULL, 0ULL};
    ull aB[3] = {0ULL, 0ULL, 0ULL};

    for (int bc = 0; bc < FBINS; bc += 64) {
        const int blen = min(64, FBINS - bc);
        __syncthreads();
        for (int i = tid; i < 12 * 64; i += 256) {
            const int kk = i >> 6, bb = i & 63;
            float vr = 0.f, vi = 0.f;
            if (bb < blen) {
                vr = kr[(kb + kk) * FBINS + bc + bb];
                vi = ki[(kb + kk) * FBINS + bc + bb];
            }
            s_r [i] = pack2(vr, vr);
            s_in[i] = pack2(-vi, -vi);
            s_ip[i] = pack2(vi, vi);
        }
        __syncthreads();
        #pragma unroll 4
        for (int bb = 0; bb < blen; bb++) {
            const int b = bc + bb;
            const ull wc = wc2[b * (FFTLEN / 2) + np];
            const ull ws = ws2[b * (FFTLEN / 2) + np];
            #pragma unroll
            for (int i = 0; i < 3; i++) {
                const int kk = (ks + 4 * i) * 64 + bb;
                const ull vr  = s_r [kk];
                const ull vin = s_in[kk];
                const ull vip = s_ip[kk];
                aA[i] = ffma2(vr,  wc, aA[i]);
                aA[i] = ffma2(vin, ws, aA[i]);
                aB[i] = ffma2(vr,  ws, aB[i]);
                aB[i] = ffma2(vip, wc, aB[i]);
            }
        }
    }
    #pragma unroll
    for (int i = 0; i < 3; i++) {
        const int k = kb + ks + 4 * i;
        ((ull*)g_A)[k * (FFTLEN / 2) + np] = aA[i];
        ((ull*)g_B)[k * (FFTLEN / 2) + np] = aB[i];
    }
}

// ---------------------------------------------------------------------------
// Main kernel: cqt[k,f] = sqrt((A[k]·frame_f)^2 + (B[k]·frame_f)^2)
// frame_f[n] = x[512*f + n]. Block = 28 bins x 64 frames, 224 threads.
// Per n-chunk of 128: stream x slice (64 frames x 128 samples) AND A/B chunk
// into smem, then packed-f32x2 rank-128 update. Smem ~62.5 KB -> 3 blocks/SM
// (21 warps) for latency hiding.
// ---------------------------------------------------------------------------
__global__ void __launch_bounds__(224, 3) cqt_main(const float* __restrict__ x,
                                                   float* __restrict__ out) {
    extern __shared__ float smem[];
    float* xs = smem;                 // FT * XR
    float* sA = smem + FT * XR;       // KT * CH
    float* sB = sA + KT * CH;

    const int tid   = threadIdx.x;
    const int lane  = tid & 31;
    const int warp  = tid >> 5;          // 0..6
    const int bf    = blockIdx.x;        // 0..255 frame tile
    const int bk    = blockIdx.y;        // 0..2 bin tile
    const int kbase = bk * KT;

    ull aR0[4], aR1[4], aI0[4], aI1[4];
    #pragma unroll
    for (int q = 0; q < 4; q++) { aR0[q] = aR1[q] = aI0[q] = aI1[q] = 0ULL; }

    const unsigned xs_u = (unsigned)__cvta_generic_to_shared(xs);
    const unsigned sA_u = (unsigned)__cvta_generic_to_shared(sA);
    const unsigned sB_u = (unsigned)__cvta_generic_to_shared(sB);
    const unsigned sA_w = sA_u + (warp * 4) * CH * 4;   // this warp's 4 bin rows
    const unsigned sB_w = sB_u + (warp * 4) * CH * 4;
    const unsigned x1u  = xs_u + (unsigned)((lane       * XR) * 4);
    const unsigned x2u  = xs_u + (unsigned)(((lane + 32) * XR) * 4);

    const float4* x4  = (const float4*)x;
    const float4* gA4 = (const float4*)g_A;
    const float4* gB4 = (const float4*)g_B;

    for (int nc = 0; nc < FFTLEN; nc += CH) {
        __syncthreads();   // protect prev chunk reads

        // stream x slice: frame f needs x[512*f + nc .. +127]
        const int xbase4 = bf * (FT * HOP / 4) + (nc >> 2);
        for (int i4 = tid; i4 < FT * (CH / 4); i4 += 224) {   // 2048 float4
            const int f  = i4 >> 5;
            const int c4 = i4 & 31;
            const int g4 = xbase4 + f * (HOP / 4) + c4;
            float4 v = make_float4(0.f, 0.f, 0.f, 0.f);
            if (g4 < T_SAMPLES / 4) v = x4[g4];
            *(float4*)(xs + f * XR + c4 * 4) = v;
        }
        // stage A/B chunk
        for (int i4 = tid; i4 < KT * CH / 4; i4 += 224) {     // 896 float4 each
            const int kk = i4 >> 5;
            const int c4 = i4 & 31;
            const int g  = (((kbase + kk) * FFTLEN + nc) >> 2) + c4;
            ((float4*)sA)[i4] = gA4[g];
            ((float4*)sB)[i4] = gB4[g];
        }
        __syncthreads();

        #pragma unroll 4
        for (int c = 0; c < CH; c += 4) {
            ull x1a, x1b, x2a, x2b;
            LDSV2(x1a, x1b, x1u + c * 4);
            LDSV2(x2a, x2b, x2u + c * 4);
            #pragma unroll
            for (int q = 0; q < 4; q++) {
                ull Aa, Ab, Ba, Bb;
                LDSV2(Aa, Ab, sA_w + (q * CH + c) * 4);
                LDSV2(Ba, Bb, sB_w + (q * CH + c) * 4);
                aR0[q] = ffma2(Aa, x1a, aR0[q]);
                aR0[q] = ffma2(Ab, x1b, aR0[q]);
                aR1[q] = ffma2(Aa, x2a, aR1[q]);
                aR1[q] = ffma2(Ab, x2b, aR1[q]);
                aI0[q] = ffma2(Ba, x1a, aI0[q]);
                aI0[q] = ffma2(Bb, x1b, aI0[q]);
                aI1[q] = ffma2(Ba, x2a, aI1[q]);
                aI1[q] = ffma2(Bb, x2b, aI1[q]);
            }
        }
    }

    // ---- epilogue: fold pair-sums, magnitude, store ----
    const int f0 = bf * FT;
    #pragma unroll
    for (int q = 0; q < 4; q++) {
        const int k = kbase + warp * 4 + q;
        const float r0v = hsum2(aR0[q]);
        const float i0v = hsum2(aI0[q]);
        const float r1v = hsum2(aR1[q]);
        const float i1v = hsum2(aI1[q]);
        const int f1 = f0 + lane;
        const int f2 = f0 + lane + 32;
        if (f1 < NFRAMES) out[k * NFRAMES + f1] = sqrtf(r0v * r0v + i0v * i0v);
        if (f2 < NFRAMES) out[k * NFRAMES + f2] = sqrtf(r1v * r1v + i1v * i1v);
    }
}

extern "C" void kernel_launch(void* const* d_in, const int* in_sizes, int n_in,
                              void* d_out, int out_size) {
    const float* x    = (const float*)d_in[0];
    const float* wcos = (const float*)d_in[1];
    const float* wsin = (const float*)d_in[2];
    const float* kr   = (const float*)d_in[3];
    const float* ki   = (const float*)d_in[4];
    float* out = (float*)d_out;

    cudaFuncSetAttribute(cqt_main, cudaFuncAttributeMaxDynamicSharedMemorySize,
                         SMEM_BYTES);

    cqt_precomp<<<dim3(16, 7), 256>>>(wcos, wsin, kr, ki);

    const int fgrids = (NFRAMES + FT - 1) / FT;   // 256
    cqt_main<<<dim3(fgrids, 3), 224, SMEM_BYTES>>>(x, out);
}

// round 9
// speedup vs baseline: 1.2421x; 1.2421x over previous
#include <cuda_runtime.h>
#include <cuda_bf16.h>
#include <math.h>

#define T_SAMPLES 8388608
#define NFRAMES   16381
#define NBINS     84
#define FBINS     1025
#define FFTLEN    2048
#define HOP       512

typedef unsigned long long ull;

// ---- fp32 combined kernels (precompute output) ----
__device__ float g_A[NBINS * FFTLEN];
__device__ float g_B[NBINS * FFTLEN];

// ---- bf16 split weights, padded MMA tiles: [32 kc][192 m][72 k] ----
#define WELEMS (32 * 192 * 72)
__device__ __nv_bfloat16 d_Whi[WELEMS];
__device__ __nv_bfloat16 d_Wlo[WELEMS];

// ---- bf16 split transposed signal: xt[k][f], [2048][16384] ----
__device__ __nv_bfloat16 d_xhi[2048ULL * 16384];
__device__ __nv_bfloat16 d_xlo[2048ULL * 16384];

// ======================= helpers =======================
__device__ __forceinline__ ull ffma2(ull a, ull b, ull c) {
    ull d; asm("fma.rn.f32x2 %0, %1, %2, %3;" : "=l"(d) : "l"(a), "l"(b), "l"(c));
    return d;
}
__device__ __forceinline__ ull pack2(float lo, float hi) {
    ull r; asm("mov.b64 %0, {%1, %2};" : "=l"(r) : "f"(lo), "f"(hi));
    return r;
}
__device__ __forceinline__ unsigned smem_u32(const void* p) {
    unsigned a;
    asm("{ .reg .u64 t; cvta.to.shared.u64 t, %1; cvt.u32.u64 %0, t; }"
        : "=r"(a) : "l"(p));
    return a;
}
#define CPA(dst, src) \
    asm volatile("cp.async.cg.shared.global [%0], [%1], 16;" :: "r"(dst), "l"(src))
#define CPCOMMIT() asm volatile("cp.async.commit_group;" ::: "memory")
#define CPWAIT1()  asm volatile("cp.async.wait_group 1;" ::: "memory")

#define LDSM4(r, a) \
    asm volatile("ldmatrix.sync.aligned.m8n8.x4.shared.b16 {%0,%1,%2,%3}, [%4];" \
        : "=r"((r)[0]), "=r"((r)[1]), "=r"((r)[2]), "=r"((r)[3]) : "r"(a))
#define LDSM4T(r, a) \
    asm volatile("ldmatrix.sync.aligned.m8n8.x4.trans.shared.b16 {%0,%1,%2,%3}, [%4];" \
        : "=r"((r)[0]), "=r"((r)[1]), "=r"((r)[2]), "=r"((r)[3]) : "r"(a))

__device__ __forceinline__ void mma16816(float* c, const unsigned* a,
                                         unsigned b0, unsigned b1) {
    asm volatile(
        "mma.sync.aligned.m16n8k16.row.col.f32.bf16.bf16.f32 "
        "{%0,%1,%2,%3}, {%4,%5,%6,%7}, {%8,%9}, {%0,%1,%2,%3};"
        : "+f"(c[0]), "+f"(c[1]), "+f"(c[2]), "+f"(c[3])
        : "r"(a[0]), "r"(a[1]), "r"(a[2]), "r"(a[3]), "r"(b0), "r"(b1));
}

__device__ __forceinline__ ull bpack4(float v0, float v1, float v2, float v3) {
    unsigned a = ((unsigned)__bfloat16_as_ushort(__float2bfloat16(v1)) << 16)
               | (unsigned)__bfloat16_as_ushort(__float2bfloat16(v0));
    unsigned b = ((unsigned)__bfloat16_as_ushort(__float2bfloat16(v3)) << 16)
               | (unsigned)__bfloat16_as_ushort(__float2bfloat16(v2));
    return ((ull)b << 32) | (ull)a;
}

// ---------------------------------------------------------------------------
// Precompute (validated R2 version): fp32 g_A/g_B.
// ---------------------------------------------------------------------------
__global__ void __launch_bounds__(256) cqt_precomp(const float* __restrict__ wcos,
                                                   const float* __restrict__ wsin,
                                                   const float* __restrict__ kr,
                                                   const float* __restrict__ ki) {
    __shared__ ull s_r[12 * 64], s_in[12 * 64], s_ip[12 * 64];
    const int tid = threadIdx.x;
    const int np  = blockIdx.x * 64 + (tid & 63);
    const int ks  = tid >> 6;
    const int kb  = blockIdx.y * 12;
    const ull* wc2 = (const ull*)wcos;
    const ull* ws2 = (const ull*)wsin;

    ull aA[3] = {0, 0, 0}, aB[3] = {0, 0, 0};
    for (int bc = 0; bc < FBINS; bc += 64) {
        const int blen = min(64, FBINS - bc);
        __syncthreads();
        for (int i = tid; i < 12 * 64; i += 256) {
            const int kk = i >> 6, bb = i & 63;
            float vr = 0.f, vi = 0.f;
            if (bb < blen) {
                vr = kr[(kb + kk) * FBINS + bc + bb];
                vi = ki[(kb + kk) * FBINS + bc + bb];
            }
            s_r[i] = pack2(vr, vr); s_in[i] = pack2(-vi, -vi); s_ip[i] = pack2(vi, vi);
        }
        __syncthreads();
        #pragma unroll 4
        for (int bb = 0; bb < blen; bb++) {
            const int b = bc + bb;
            const ull wc = wc2[b * (FFTLEN / 2) + np];
            const ull ws = ws2[b * (FFTLEN / 2) + np];
            #pragma unroll
            for (int i = 0; i < 3; i++) {
                const int kk = (ks + 4 * i) * 64 + bb;
                aA[i] = ffma2(s_r[kk], wc, aA[i]);
                aA[i] = ffma2(s_in[kk], ws, aA[i]);
                aB[i] = ffma2(s_r[kk], ws, aB[i]);
                aB[i] = ffma2(s_ip[kk], wc, aB[i]);
            }
        }
    }
    #pragma unroll
    for (int i = 0; i < 3; i++) {
        const int k = kb + ks + 4 * i;
        ((ull*)g_A)[k * (FFTLEN / 2) + np] = aA[i];
        ((ull*)g_B)[k * (FFTLEN / 2) + np] = aB[i];
    }
}

// ---------------------------------------------------------------------------
// Repack: fp32 g_A/g_B -> bf16 hi/lo tiles [32 kc][192 m][72 kpad].
// Rows 0-83 = A (R), 96-179 = B (I), rest zero; k pad cols zero.
// ---------------------------------------------------------------------------
__global__ void __launch_bounds__(256) cqt_repack() {
    const int i = blockIdx.x * 256 + threadIdx.x;
    if (i >= WELEMS) return;
    const int kc = i / (192 * 72);
    const int r  = i % (192 * 72);
    const int m  = r / 72;
    const int kp = r % 72;
    float v = 0.f;
    if (kp < 64) {
        const int n = kc * 64 + kp;
        if (m < NBINS) v = g_A[m * FFTLEN + n];
        else if (m >= 96 && m < 96 + NBINS) v = g_B[(m - 96) * FFTLEN + n];
    }
    const __nv_bfloat16 h = __float2bfloat16(v);
    d_Whi[i] = h;
    d_Wlo[i] = __float2bfloat16(v - __bfloat162float(h));
}

// ---------------------------------------------------------------------------
// x transpose + split: xt[k][f] = bf16hi/lo(x[512 f + k]); OOB -> 0.
// Block: 64 f x 64 k tile via smem. Grid (256, 32).
// ---------------------------------------------------------------------------
__global__ void __launch_bounds__(256) cqt_xsplit(const float* __restrict__ x) {
    __shared__ float tile[64][68];
    const int tid = threadIdx.x;
    const int f0 = blockIdx.x * 64;
    const int k0 = blockIdx.y * 64;

    for (int i = tid; i < 1024; i += 256) {
        const int f = i >> 4, q = (i & 15) * 4;
        const long base = (long)(f0 + f) * HOP + k0 + q;
        float4 v;
        if (base + 3 < T_SAMPLES) {
            v = *(const float4*)(x + base);
        } else {
            v.x = (base + 0 < T_SAMPLES) ? x[base + 0] : 0.f;
            v.y = (base + 1 < T_SAMPLES) ? x[base + 1] : 0.f;
            v.z = (base + 2 < T_SAMPLES) ? x[base + 2] : 0.f;
            v.w = (base + 3 < T_SAMPLES) ? x[base + 3] : 0.f;
        }
        *(float4*)&tile[f][q] = v;
    }
    __syncthreads();
    for (int i = tid; i < 1024; i += 256) {
        const int k = i >> 4, fq = (i & 15) * 4;
        float v[4], h[4], l[4];
        #pragma unroll
        for (int j = 0; j < 4; j++) {
            v[j] = tile[fq + j][k];
            h[j] = __bfloat162float(__float2bfloat16(v[j]));
            l[j] = v[j] - h[j];
        }
        const size_t o = (size_t)(k0 + k) * 16384 + f0 + fq;
        *(ull*)(d_xhi + o) = bpack4(h[0], h[1], h[2], h[3]);
        *(ull*)(d_xlo + o) = bpack4(l[0], l[1], l[2], l[3]);
    }
}

// ---------------------------------------------------------------------------
// Main HMMA GEMM: D[192,16384] = W[192,2048] * X, 3 bf16 passes.
// Block = 64 frames, 8 warps = 4 M-stripes(48) x 2 N-halves(32).
// 96 stages (3 passes x 32 K64-chunks), cp.async double-buffered.
// Epilogue: I-stripes -> smem, R-stripes combine sqrt(R^2+I^2).
// ---------------------------------------------------------------------------
#define AST    144                 // A row stride bytes (72 bf16)
#define XST    144                 // X row stride bytes
#define ABYTES (192 * 144)         // 27648
#define XBYTES (64 * 144)          // 9216
#define STG    (ABYTES + XBYTES)   // 36864
#define BUF0   1024
#define SMEM_MAIN (BUF0 + 2 * STG) // 74752

__global__ void __launch_bounds__(256, 2) cqt_mma(float* __restrict__ out) {
    extern __shared__ __align__(128) char dsm[];
    const unsigned sb = smem_u32(dsm);
    const int tid  = threadIdx.x;
    const int lane = tid & 31;
    const int wid  = tid >> 5;
    const int ms   = wid >> 1;        // 0..3 M-stripe (48 rows)
    const int nh   = wid & 1;         // 0..1 N-half (32 cols)
    const int f0   = blockIdx.x * 64;

    float acc[3][4][4];
    #pragma unroll
    for (int t = 0; t < 3; t++)
        #pragma unroll
        for (int nn = 0; nn < 4; nn++)
            #pragma unroll
            for (int j = 0; j < 4; j++) acc[t][nn][j] = 0.f;

    auto stage = [&](int s, int b) {
        const int p  = s >> 5;        // pass: 0 hi*hi, 1 hi*lo, 2 lo*hi
        const int kc = s & 31;
        const char* wsrc = (const char*)(p < 2 ? d_Whi : d_Wlo) + (size_t)kc * ABYTES;
        const char* xsrc = (const char*)(p == 1 ? d_xlo : d_xhi);
        const unsigned abuf = sb + BUF0 + b * STG;
        const unsigned xbuf = abuf + ABYTES;
        for (int i = tid; i < ABYTES / 16; i += 256)          // 1728
            CPA(abuf + i * 16, wsrc + i * 16);
        const char* xb = xsrc + ((size_t)(kc * 64) * 16384 + f0) * 2;
        for (int i = tid; i < 512; i += 256) {                // 64 rows x 8
            const int kr = i >> 3, sg = i & 7;
            CPA(xbuf + kr * XST + sg * 16, xb + (size_t)kr * 32768 + sg * 16);
        }
        CPCOMMIT();
    };

    stage(0, 0);
    stage(1, 1);

    for (int s = 0; s < 96; s++) {
        const int b = s & 1;
        CPWAIT1();
        __syncthreads();
        const unsigned abase = sb + BUF0 + b * STG + ms * (48 * AST);
        const unsigned xbase = sb + BUF0 + b * STG + ABYTES + nh * 64;
        #pragma unroll
        for (int k16 = 0; k16 < 4; k16++) {
            const unsigned a0r = abase + (lane & 15) * AST + (lane >> 4) * 16 + k16 * 32;
            unsigned af[3][4];
            LDSM4(af[0], a0r);
            LDSM4(af[1], a0r + 16 * AST);
            LDSM4(af[2], a0r + 32 * AST);
            const unsigned xr = xbase + (unsigned)((k16 * 16 + (lane & 15)) * XST)
                              + (lane >> 4) * 16;
            unsigned bfr[2][4];
            LDSM4T(bfr[0], xr);
            LDSM4T(bfr[1], xr + 32);
            #pragma unroll
            for (int t = 0; t < 3; t++) {
                mma16816(acc[t][0], af[t], bfr[0][0], bfr[0][1]);
                mma16816(acc[t][1], af[t], bfr[0][2], bfr[0][3]);
                mma16816(acc[t][2], af[t], bfr[1][0], bfr[1][1]);
                mma16816(acc[t][3], af[t], bfr[1][2], bfr[1][3]);
            }
        }
        __syncthreads();
        if (s + 2 < 96) stage(s + 2, b);
    }

    // ---- epilogue: combine R (rows 0-95) with I (rows 96-191) ----
    __syncthreads();
    float* sI = (float*)(dsm + BUF0);          // [96][66]
    if (ms >= 2) {
        #pragma unroll
        for (int t = 0; t < 3; t++)
            #pragma unroll
            for (int nn = 0; nn < 4; nn++) {
                const int mi = (ms - 2) * 48 + t * 16 + (lane >> 2);
                const int nl = nh * 32 + nn * 8 + 2 * (lane & 3);
                sI[mi * 66 + nl]           = acc[t][nn][0];
                sI[mi * 66 + nl + 1]       = acc[t][nn][1];
                sI[(mi + 8) * 66 + nl]     = acc[t][nn][2];
                sI[(mi + 8) * 66 + nl + 1] = acc[t][nn][3];
            }
    }
    __syncthreads();
    if (ms < 2) {
        #pragma unroll
        for (int t = 0; t < 3; t++)
            #pragma unroll
            for (int nn = 0; nn < 4; nn++) {
                const int m0 = ms * 48 + t * 16 + (lane >> 2);
                const int nl = nh * 32 + nn * 8 + 2 * (lane & 3);
                const int f  = f0 + nl;
                #pragma unroll
                for (int half = 0; half < 2; half++) {
                    const int m = m0 + half * 8;
                    if (m < NBINS) {
                        const float r0 = acc[t][nn][half * 2];
                        const float r1 = acc[t][nn][half * 2 + 1];
                        const float i0 = sI[m * 66 + nl];
                        const float i1 = sI[m * 66 + nl + 1];
                        if (f < NFRAMES)
                            out[m * NFRAMES + f] = sqrtf(r0 * r0 + i0 * i0);
                        if (f + 1 < NFRAMES)
                            out[m * NFRAMES + f + 1] = sqrtf(r1 * r1 + i1 * i1);
                    }
                }
            }
    }
}

extern "C" void kernel_launch(void* const* d_in, const int* in_sizes, int n_in,
                              void* d_out, int out_size) {
    const float* x    = (const float*)d_in[0];
    const float* wcos = (const float*)d_in[1];
    const float* wsin = (const float*)d_in[2];
    const float* kr   = (const float*)d_in[3];
    const float* ki   = (const float*)d_in[4];
    float* out = (float*)d_out;

    cudaFuncSetAttribute(cqt_mma, cudaFuncAttributeMaxDynamicSharedMemorySize,
                         SMEM_MAIN);

    cqt_precomp<<<dim3(16, 7), 256>>>(wcos, wsin, kr, ki);
    cqt_repack<<<(WELEMS + 255) / 256, 256>>>();
    cqt_xsplit<<<dim3(256, 32), 256>>>(x);
    cqt_mma<<<256, 256, SMEM_MAIN>>>(out);
}

// round 11
// speedup vs baseline: 2.3537x; 1.8949x over previous
#include <cuda_runtime.h>
#include <cuda_bf16.h>
#include <math.h>

#define T_SAMPLES 8388608
#define NFRAMES   16381
#define NBINS     84
#define FBINS     1025
#define FFTLEN    2048
#define HOP       512

typedef unsigned long long ull;

// ---- fp32 combined kernels, split into two b-half partials ----
__device__ float g_A0[NBINS * FFTLEN];
__device__ float g_A1[NBINS * FFTLEN];
__device__ float g_B0[NBINS * FFTLEN];
__device__ float g_B1[NBINS * FFTLEN];

// ---- bf16 split weights, padded MMA tiles: [32 kc][192 m][72 k] ----
#define WELEMS (32 * 192 * 72)
__device__ __nv_bfloat16 d_Whi[WELEMS];
__device__ __nv_bfloat16 d_Wlo[WELEMS];

// ======================= helpers =======================
__device__ __forceinline__ ull ffma2(ull a, ull b, ull c) {
    ull d; asm("fma.rn.f32x2 %0, %1, %2, %3;" : "=l"(d) : "l"(a), "l"(b), "l"(c));
    return d;
}
__device__ __forceinline__ ull pack2(float lo, float hi) {
    ull r; asm("mov.b64 %0, {%1, %2};" : "=l"(r) : "f"(lo), "f"(hi));
    return r;
}
__device__ __forceinline__ unsigned smem_u32(const void* p) {
    unsigned a;
    asm("{ .reg .u64 t; cvta.to.shared.u64 t, %1; cvt.u32.u64 %0, t; }"
        : "=r"(a) : "l"(p));
    return a;
}
#define CPA(dst, src) \
    asm volatile("cp.async.cg.shared.global [%0], [%1], 16;" :: "r"(dst), "l"(src))
#define CPA_Z(dst, src, nb) \
    asm volatile("cp.async.cg.shared.global [%0], [%1], 16, %2;" \
                 :: "r"(dst), "l"(src), "r"(nb))
#define CPCOMMIT() asm volatile("cp.async.commit_group;" ::: "memory")
#define CPWAIT1()  asm volatile("cp.async.wait_group 1;" ::: "memory")

#define LDSM4(r, a) \
    asm volatile("ldmatrix.sync.aligned.m8n8.x4.shared.b16 {%0,%1,%2,%3}, [%4];" \
        : "=r"((r)[0]), "=r"((r)[1]), "=r"((r)[2]), "=r"((r)[3]) : "r"(a))
#define LDSM4T(r, a) \
    asm volatile("ldmatrix.sync.aligned.m8n8.x4.trans.shared.b16 {%0,%1,%2,%3}, [%4];" \
        : "=r"((r)[0]), "=r"((r)[1]), "=r"((r)[2]), "=r"((r)[3]) : "r"(a))

__device__ __forceinline__ void mma16816(float* c, const unsigned* a,
                                         unsigned b0, unsigned b1) {
    asm volatile(
        "mma.sync.aligned.m16n8k16.row.col.f32.bf16.bf16.f32 "
        "{%0,%1,%2,%3}, {%4,%5,%6,%7}, {%8,%9}, {%0,%1,%2,%3};"
        : "+f"(c[0]), "+f"(c[1]), "+f"(c[2]), "+f"(c[3])
        : "r"(a[0]), "r"(a[1]), "r"(a[2]), "r"(a[3]), "r"(b0), "r"(b1));
}

// ---------------------------------------------------------------------------
// Precompute: fp32 partial combined kernels, b-halves split over blockIdx.z.
// ---------------------------------------------------------------------------
__global__ void __launch_bounds__(256) cqt_precomp(const float* __restrict__ wcos,
                                                   const float* __restrict__ wsin,
                                                   const float* __restrict__ kr,
                                                   const float* __restrict__ ki) {
    __shared__ ull s_r[12 * 64], s_in[12 * 64], s_ip[12 * 64];
    const int tid  = threadIdx.x;
    const int np   = blockIdx.x * 64 + (tid & 63);
    const int ks   = tid >> 6;
    const int kb   = blockIdx.y * 12;
    const int half = blockIdx.z;
    const int bc0  = half * 512;
    const int bcE  = half ? FBINS : 512;
    const ull* wc2 = (const ull*)wcos;
    const ull* ws2 = (const ull*)wsin;
    float* outA = half ? g_A1 : g_A0;
    float* outB = half ? g_B1 : g_B0;

    ull aA[3] = {0, 0, 0}, aB[3] = {0, 0, 0};
    for (int bc = bc0; bc < bcE; bc += 64) {
        const int blen = min(64, bcE - bc);
        __syncthreads();
        for (int i = tid; i < 12 * 64; i += 256) {
            const int kk = i >> 6, bb = i & 63;
            float vr = 0.f, vi = 0.f;
            if (bb < blen) {
                vr = kr[(kb + kk) * FBINS + bc + bb];
                vi = ki[(kb + kk) * FBINS + bc + bb];
            }
            s_r[i] = pack2(vr, vr); s_in[i] = pack2(-vi, -vi); s_ip[i] = pack2(vi, vi);
        }
        __syncthreads();
        #pragma unroll 4
        for (int bb = 0; bb < blen; bb++) {
            const int b = bc + bb;
            const ull wc = wc2[b * (FFTLEN / 2) + np];
            const ull ws = ws2[b * (FFTLEN / 2) + np];
            #pragma unroll
            for (int i = 0; i < 3; i++) {
                const int kk = (ks + 4 * i) * 64 + bb;
                aA[i] = ffma2(s_r[kk], wc, aA[i]);
                aA[i] = ffma2(s_in[kk], ws, aA[i]);
                aB[i] = ffma2(s_r[kk], ws, aB[i]);
                aB[i] = ffma2(s_ip[kk], wc, aB[i]);
            }
        }
    }
    #pragma unroll
    for (int i = 0; i < 3; i++) {
        const int k = kb + ks + 4 * i;
        ((ull*)outA)[k * (FFTLEN / 2) + np] = aA[i];
        ((ull*)outB)[k * (FFTLEN / 2) + np] = aB[i];
    }
}

// ---------------------------------------------------------------------------
// Repack: sum partials -> bf16 hi/lo tiles [32 kc][192 m][72 kpad].
// Rows 0-83 = A (R), 96-179 = B (I), rest zero; k pad cols zero.
// ---------------------------------------------------------------------------
__global__ void __launch_bounds__(256) cqt_repack() {
    const int i = blockIdx.x * 256 + threadIdx.x;
    if (i >= WELEMS) return;
    const int kc = i / (192 * 72);
    const int r  = i % (192 * 72);
    const int m  = r / 72;
    const int kp = r % 72;
    float v = 0.f;
    if (kp < 64) {
        const int n = kc * 64 + kp;
        if (m < NBINS) v = g_A0[m * FFTLEN + n] + g_A1[m * FFTLEN + n];
        else if (m >= 96 && m < 96 + NBINS)
            v = g_B0[(m - 96) * FFTLEN + n] + g_B1[(m - 96) * FFTLEN + n];
    }
    const __nv_bfloat16 h = __float2bfloat16(v);
    d_Whi[i] = h;
    d_Wlo[i] = __float2bfloat16(v - __bfloat162float(h));
}

// ---------------------------------------------------------------------------
// Main HMMA GEMM with in-kernel x convert.
// D[192,16384] = W[192,2048] * X; 3 bf16 combos folded per K-chunk.
// Block = 128 frames, 8 warps = 4 M-stripes(48) x 2 N-halves(64 f). Grid 128.
// Per stage (kc): cp.async Whi+Wlo (55KB) + X fp32 (34KB, straight from x),
// convert fp32 -> bf16 hi/lo [k][f] tiles in smem, 288 mma/warp.
// ---------------------------------------------------------------------------
#define AST    144                  // W row stride bytes (72 bf16)
#define ABYTES (192 * 144)          // 27648
#define XFST   272                  // fp32 X row stride bytes (68 floats)
#define XF32B  (128 * XFST)         // 34816
#define STG    (2 * ABYTES + XF32B) // 90112
#define XTST   272                  // bf16 X tile row stride (136 bf16)
#define XTILE  (64 * XTST)          // 17408
#define XH_OFF 0
#define XL_OFF XTILE
#define STG0   (2 * XTILE)          // 34816
#define SMEM_MAIN (STG0 + 2 * STG)  // 215040

__global__ void __launch_bounds__(256, 1) cqt_mma(const float* __restrict__ x,
                                                  float* __restrict__ out) {
    extern __shared__ __align__(128) char dsm[];
    const unsigned sb = smem_u32(dsm);
    const int tid  = threadIdx.x;
    const int lane = tid & 31;
    const int wid  = tid >> 5;
    const int ms   = wid >> 1;        // 0..3 M-stripe (48 rows)
    const int nh   = wid & 1;         // 0..1 N-half (64 frames)
    const int f0   = blockIdx.x * 128;

    float acc[3][8][4];
    #pragma unroll
    for (int t = 0; t < 3; t++)
        #pragma unroll
        for (int nn = 0; nn < 8; nn++)
            #pragma unroll
            for (int j = 0; j < 4; j++) acc[t][nn][j] = 0.f;

    auto stage = [&](int kc, int b) {
        const unsigned sbuf = sb + STG0 + b * STG;
        const char* whi = (const char*)d_Whi + (size_t)kc * ABYTES;
        const char* wlo = (const char*)d_Wlo + (size_t)kc * ABYTES;
        for (int i = tid; i < ABYTES / 16; i += 256) {        // 1728
            CPA(sbuf + i * 16, whi + i * 16);
            CPA(sbuf + ABYTES + i * 16, wlo + i * 16);
        }
        const unsigned xf = sbuf + 2 * ABYTES;
        for (int i = tid; i < 2048; i += 256) {               // 128 f x 16 segs
            const int f = i >> 4, seg = i & 15;
            const long gi = (long)(f0 + f) * HOP + kc * 64 + seg * 4;
            const long rem = (long)T_SAMPLES - gi;
            const int nb = rem >= 4 ? 16 : (rem > 0 ? (int)rem * 4 : 0);
            CPA_Z(xf + f * XFST + seg * 16, x + gi, nb);
        }
        CPCOMMIT();
    };

    stage(0, 0);
    stage(1, 1);

    for (int kc = 0; kc < 32; kc++) {
        const int b = kc & 1;
        CPWAIT1();
        __syncthreads();

        // ---- convert fp32 [f][k] -> bf16 hi/lo [k][f] tiles ----
        {
            const float* xfp = (const float*)(dsm + STG0 + b * STG + 2 * ABYTES);
            const int kk  = tid & 63;
            const int oct = tid >> 6;      // f-range oct*32..+31
            #pragma unroll
            for (int g = 0; g < 4; g++) {
                unsigned h[4], l[4];
                #pragma unroll
                for (int p = 0; p < 4; p++) {
                    const int f = oct * 32 + g * 8 + p * 2;
                    const float v0 = xfp[f * 68 + kk];
                    const float v1 = xfp[(f + 1) * 68 + kk];
                    __nv_bfloat162 hb = __float22bfloat162_rn(make_float2(v0, v1));
                    const float2 hf = __bfloat1622float2(hb);
                    __nv_bfloat162 lb =
                        __float22bfloat162_rn(make_float2(v0 - hf.x, v1 - hf.y));
                    h[p] = *(unsigned*)&hb;
                    l[p] = *(unsigned*)&lb;
                }
                const int fo = oct * 32 + g * 8;
                *(uint4*)(dsm + XH_OFF + kk * XTST + fo * 2) =
                    make_uint4(h[0], h[1], h[2], h[3]);
                *(uint4*)(dsm + XL_OFF + kk * XTST + fo * 2) =
                    make_uint4(l[0], l[1], l[2], l[3]);
            }
        }
        __syncthreads();

        // ---- MMA: 3 combos per k16 ----
        const unsigned abhi = sb + STG0 + b * STG + ms * (48 * AST);
        const unsigned ablo = abhi + ABYTES;
        const unsigned xh = sb + XH_OFF + nh * 128;
        const unsigned xl = sb + XL_OFF + nh * 128;
        #pragma unroll
        for (int k16 = 0; k16 < 4; k16++) {
            const unsigned arow = (lane & 15) * AST + (lane >> 4) * 16 + k16 * 32;
            unsigned ahi[3][4], alo[3][4];
            LDSM4(ahi[0], abhi + arow);
            LDSM4(ahi[1], abhi + arow + 16 * AST);
            LDSM4(ahi[2], abhi + arow + 32 * AST);
            LDSM4(alo[0], ablo + arow);
            LDSM4(alo[1], ablo + arow + 16 * AST);
            LDSM4(alo[2], ablo + arow + 32 * AST);
            const unsigned xrow = (unsigned)((k16 * 16 + (lane & 15)) * XTST)
                                + (lane >> 4) * 16;
            unsigned bh[4][4], bl[4][4];
            #pragma unroll
            for (int g = 0; g < 4; g++) LDSM4T(bh[g], xh + xrow + g * 32);
            #pragma unroll
            for (int g = 0; g < 4; g++) LDSM4T(bl[g], xl + xrow + g * 32);
            #pragma unroll
            for (int t = 0; t < 3; t++) {
                #pragma unroll
                for (int g = 0; g < 4; g++) {
                    mma16816(acc[t][2 * g],     ahi[t], bh[g][0], bh[g][1]);
                    mma16816(acc[t][2 * g + 1], ahi[t], bh[g][2], bh[g][3]);
                    mma16816(acc[t][2 * g],     alo[t], bh[g][0], bh[g][1]);
                    mma16816(acc[t][2 * g + 1], alo[t], bh[g][2], bh[g][3]);
                    mma16816(acc[t][2 * g],     ahi[t], bl[g][0], bl[g][1]);
                    mma16816(acc[t][2 * g + 1], ahi[t], bl[g][2], bl[g][3]);
                }
            }
        }
        __syncthreads();
        if (kc + 2 < 32) stage(kc + 2, b);
    }

    // ---- epilogue: I-stripes -> smem, R-stripes combine ----
    __syncthreads();
    float* sI = (float*)dsm;          // [96][132]
    if (ms >= 2) {
        #pragma unroll
        for (int t = 0; t < 3; t++)
            #pragma unroll
            for (int nn = 0; nn < 8; nn++) {
                const int mi = (ms - 2) * 48 + t * 16 + (lane >> 2);
                const int nl = nh * 64 + nn * 8 + 2 * (lane & 3);
                sI[mi * 132 + nl]           = acc[t][nn][0];
                sI[mi * 132 + nl + 1]       = acc[t][nn][1];
                sI[(mi + 8) * 132 + nl]     = acc[t][nn][2];
                sI[(mi + 8) * 132 + nl + 1] = acc[t][nn][3];
            }
    }
    __syncthreads();
    if (ms < 2) {
        #pragma unroll
        for (int t = 0; t < 3; t++)
            #pragma unroll
            for (int nn = 0; nn < 8; nn++) {
                const int m0 = ms * 48 + t * 16 + (lane >> 2);
                const int nl = nh * 64 + nn * 8 + 2 * (lane & 3);
                const int f  = f0 + nl;
                #pragma unroll
                for (int half = 0; half < 2; half++) {
                    const int m = m0 + half * 8;
                    if (m < NBINS) {
                        const float r0 = acc[t][nn][half * 2];
                        const float r1 = acc[t][nn][half * 2 + 1];
                        const float i0 = sI[m * 132 + nl];
                        const float i1 = sI[m * 132 + nl + 1];
                        if (f < NFRAMES)
                            out[m * NFRAMES + f] = sqrtf(r0 * r0 + i0 * i0);
                        if (f + 1 < NFRAMES)
                            out[m * NFRAMES + f + 1] = sqrtf(r1 * r1 + i1 * i1);
                    }
                }
            }
    }
}

extern "C" void kernel_launch(void* const* d_in, const int* in_sizes, int n_in,
                              void* d_out, int out_size) {
    const float* x    = (const float*)d_in[0];
    const float* wcos = (const float*)d_in[1];
    const float* wsin = (const float*)d_in[2];
    const float* kr   = (const float*)d_in[3];
    const float* ki   = (const float*)d_in[4];
    float* out = (float*)d_out;

    cudaFuncSetAttribute(cqt_mma, cudaFuncAttributeMaxDynamicSharedMemorySize,
                         SMEM_MAIN);

    cqt_precomp<<<dim3(16, 7, 2), 256>>>(wcos, wsin, kr, ki);
    cqt_repack<<<(WELEMS + 255) / 256, 256>>>();
    cqt_mma<<<128, 256, SMEM_MAIN>>>(x, out);
}

// round 12
// speedup vs baseline: 2.4563x; 1.0436x over previous
#include <cuda_runtime.h>
#include <cuda_bf16.h>
#include <math.h>

#define T_SAMPLES 8388608
#define NFRAMES   16381
#define NBINS     84
#define FBINS     1025
#define FFTLEN    2048
#define HOP       512

typedef unsigned long long ull;

// ---- product matrix P[192][4096] = [kr;ki] @ [wcos | wsin], two K-half partials
__device__ float g_P0[192 * 4096];
__device__ float g_P1[192 * 4096];

// ---- bf16 split weights, padded MMA tiles: [32 kc][192 m][72 k] ----
#define WELEMS (32 * 192 * 72)
__device__ __nv_bfloat16 d_Whi[WELEMS];
__device__ __nv_bfloat16 d_Wlo[WELEMS];

// ======================= helpers =======================
__device__ __forceinline__ unsigned smem_u32(const void* p) {
    unsigned a;
    asm("{ .reg .u64 t; cvta.to.shared.u64 t, %1; cvt.u32.u64 %0, t; }"
        : "=r"(a) : "l"(p));
    return a;
}
#define CPA(dst, src) \
    asm volatile("cp.async.cg.shared.global [%0], [%1], 16;" :: "r"(dst), "l"(src))
#define CPA_Z(dst, src, nb) \
    asm volatile("cp.async.cg.shared.global [%0], [%1], 16, %2;" \
                 :: "r"(dst), "l"(src), "r"(nb))
#define CPCOMMIT() asm volatile("cp.async.commit_group;" ::: "memory")
#define CPWAIT1()  asm volatile("cp.async.wait_group 1;" ::: "memory")

#define LDSM4(r, a) \
    asm volatile("ldmatrix.sync.aligned.m8n8.x4.shared.b16 {%0,%1,%2,%3}, [%4];" \
        : "=r"((r)[0]), "=r"((r)[1]), "=r"((r)[2]), "=r"((r)[3]) : "r"(a))
#define LDSM4T(r, a) \
    asm volatile("ldmatrix.sync.aligned.m8n8.x4.trans.shared.b16 {%0,%1,%2,%3}, [%4];" \
        : "=r"((r)[0]), "=r"((r)[1]), "=r"((r)[2]), "=r"((r)[3]) : "r"(a))

__device__ __forceinline__ void mma16816(float* c, const unsigned* a,
                                         unsigned b0, unsigned b1) {
    asm volatile(
        "mma.sync.aligned.m16n8k16.row.col.f32.bf16.bf16.f32 "
        "{%0,%1,%2,%3}, {%4,%5,%6,%7}, {%8,%9}, {%0,%1,%2,%3};"
        : "+f"(c[0]), "+f"(c[1]), "+f"(c[2]), "+f"(c[3])
        : "r"(a[0]), "r"(a[1]), "r"(a[2]), "r"(a[3]), "r"(b0), "r"(b1));
}

__device__ __forceinline__ void bsplit2(float v0, float v1,
                                        unsigned& h, unsigned& l) {
    __nv_bfloat162 hb = __float22bfloat162_rn(make_float2(v0, v1));
    const float2 hf = __bfloat1622float2(hb);
    __nv_bfloat162 lb = __float22bfloat162_rn(make_float2(v0 - hf.x, v1 - hf.y));
    h = *(unsigned*)&hb;
    l = *(unsigned*)&lb;
}

// ---------------------------------------------------------------------------
// Precompute GEMM: P[192,4096] = [kr(0-83); ki(96-179)] @ [wcos | wsin].
// Split-bf16 3-combo HMMA. Grid (64 n-tiles, 2 K-halves); block 192m x 64n,
// 8 warps = 4 M-stripes(48) x 2 N-halves(32). Per K64 chunk: LDG fp32
// operands (L2-resident), convert to bf16 hi/lo smem tiles, MMA.
// ---------------------------------------------------------------------------
#define PAST 144                    // A tile row stride bytes (72 bf16)
#define PAH  0
#define PAL  (192 * 144)            // 27648
#define PXH  (2 * 192 * 144)        // 55296
#define PXL  (PXH + 64 * 144)       // 64512
#define SMEM_PG (PXL + 64 * 144)    // 73728

__global__ void __launch_bounds__(256, 1) cqt_pgemm(const float* __restrict__ wcos,
                                                    const float* __restrict__ wsin,
                                                    const float* __restrict__ kr,
                                                    const float* __restrict__ ki) {
    extern __shared__ __align__(128) char psm[];
    const unsigned sb = smem_u32(psm);
    const int tid  = threadIdx.x;
    const int lane = tid & 31;
    const int wid  = tid >> 5;
    const int ms   = wid >> 1;        // 0..3 M-stripe (48 rows)
    const int nh   = wid & 1;         // 0..1 N-half (32 cols)
    const int n0   = blockIdx.x * 64;
    const int half = blockIdx.y;
    const float* xsrc = (n0 < 2048) ? (wcos + n0) : (wsin + (n0 - 2048));
    const int nchunks = half ? 9 : 8;
    const int b0base  = half * 512;

    float acc[3][4][4];
    #pragma unroll
    for (int t = 0; t < 3; t++)
        #pragma unroll
        for (int nn = 0; nn < 4; nn++)
            #pragma unroll
            for (int j = 0; j < 4; j++) acc[t][nn][j] = 0.f;

    for (int c = 0; c < nchunks; c++) {
        const int b0 = b0base + c * 64;
        __syncthreads();
        // stage A (kr/ki) fp32 -> bf16 hi/lo tile [192][72]
        for (int i2 = tid; i2 < 6144; i2 += 256) {
            const int m  = i2 >> 5;
            const int bb = (i2 & 31) * 2;
            const int b  = b0 + bb;
            float v0 = 0.f, v1 = 0.f;
            if (m < NBINS) {
                const float* row = kr + m * FBINS;
                if (b < FBINS)     v0 = row[b];
                if (b + 1 < FBINS) v1 = row[b + 1];
            } else if (m >= 96 && m < 96 + NBINS) {
                const float* row = ki + (m - 96) * FBINS;
                if (b < FBINS)     v0 = row[b];
                if (b + 1 < FBINS) v1 = row[b + 1];
            }
            unsigned h, l;
            bsplit2(v0, v1, h, l);
            *(unsigned*)(psm + PAH + m * PAST + bb * 2) = h;
            *(unsigned*)(psm + PAL + m * PAST + bb * 2) = l;
        }
        // stage X (wcos/wsin) fp32 -> bf16 hi/lo tile [64 b][72 n]
        for (int i2 = tid; i2 < 2048; i2 += 256) {
            const int bb = i2 >> 5;
            const int nn = (i2 & 31) * 2;
            const int b  = b0 + bb;
            float2 v = make_float2(0.f, 0.f);
            if (b < FBINS) v = *(const float2*)(xsrc + (size_t)b * FFTLEN + nn);
            unsigned h, l;
            bsplit2(v.x, v.y, h, l);
            *(unsigned*)(psm + PXH + bb * PAST + nn * 2) = h;
            *(unsigned*)(psm + PXL + bb * PAST + nn * 2) = l;
        }
        __syncthreads();

        const unsigned abhi = sb + PAH + ms * (48 * PAST);
        const unsigned ablo = sb + PAL + ms * (48 * PAST);
        const unsigned xh   = sb + PXH + nh * 64;
        const unsigned xl   = sb + PXL + nh * 64;
        #pragma unroll
        for (int k16 = 0; k16 < 4; k16++) {
            const unsigned arow = (lane & 15) * PAST + (lane >> 4) * 16 + k16 * 32;
            unsigned ahi[3][4], alo[3][4];
            LDSM4(ahi[0], abhi + arow);
            LDSM4(ahi[1], abhi + arow + 16 * PAST);
            LDSM4(ahi[2], abhi + arow + 32 * PAST);
            LDSM4(alo[0], ablo + arow);
            LDSM4(alo[1], ablo + arow + 16 * PAST);
            LDSM4(alo[2], ablo + arow + 32 * PAST);
            const unsigned xrow = (unsigned)((k16 * 16 + (lane & 15)) * PAST)
                                + (lane >> 4) * 16;
            unsigned bh[2][4], bl[2][4];
            #pragma unroll
            for (int g = 0; g < 2; g++) LDSM4T(bh[g], xh + xrow + g * 32);
            #pragma unroll
            for (int g = 0; g < 2; g++) LDSM4T(bl[g], xl + xrow + g * 32);
            #pragma unroll
            for (int t = 0; t < 3; t++) {
                #pragma unroll
                for (int g = 0; g < 2; g++) {
                    mma16816(acc[t][2 * g],     ahi[t], bh[g][0], bh[g][1]);
                    mma16816(acc[t][2 * g + 1], ahi[t], bh[g][2], bh[g][3]);
                    mma16816(acc[t][2 * g],     alo[t], bh[g][0], bh[g][1]);
                    mma16816(acc[t][2 * g + 1], alo[t], bh[g][2], bh[g][3]);
                    mma16816(acc[t][2 * g],     ahi[t], bl[g][0], bl[g][1]);
                    mma16816(acc[t][2 * g + 1], ahi[t], bl[g][2], bl[g][3]);
                }
            }
        }
    }

    float* P = half ? g_P1 : g_P0;
    #pragma unroll
    for (int t = 0; t < 3; t++)
        #pragma unroll
        for (int nn = 0; nn < 4; nn++) {
            const int m = ms * 48 + t * 16 + (lane >> 2);
            const int n = n0 + nh * 32 + nn * 8 + 2 * (lane & 3);
            P[m * 4096 + n]           = acc[t][nn][0];
            P[m * 4096 + n + 1]       = acc[t][nn][1];
            P[(m + 8) * 4096 + n]     = acc[t][nn][2];
            P[(m + 8) * 4096 + n + 1] = acc[t][nn][3];
        }
}

// ---------------------------------------------------------------------------
// Repack: combine P partials -> W bf16 hi/lo tiles [32 kc][192 m][72 kpad].
// A[m][n] = P[m][n] - P[m+96][2048+n];  B[k][n] = P[k][2048+n] + P[k+96][n].
// ---------------------------------------------------------------------------
__global__ void __launch_bounds__(256) cqt_repack() {
    const int i = blockIdx.x * 256 + threadIdx.x;
    if (i >= WELEMS) return;
    const int kc = i / (192 * 72);
    const int r  = i % (192 * 72);
    const int m  = r / 72;
    const int kp = r % 72;
    float v = 0.f;
    if (kp < 64) {
        const int n = kc * 64 + kp;
        if (m < NBINS) {
            v = (g_P0[m * 4096 + n] + g_P1[m * 4096 + n])
              - (g_P0[(m + 96) * 4096 + 2048 + n] + g_P1[(m + 96) * 4096 + 2048 + n]);
        } else if (m >= 96 && m < 96 + NBINS) {
            const int k = m - 96;
            v = (g_P0[k * 4096 + 2048 + n] + g_P1[k * 4096 + 2048 + n])
              + (g_P0[m * 4096 + n] + g_P1[m * 4096 + n]);
        }
    }
    const __nv_bfloat16 h = __float2bfloat16(v);
    d_Whi[i] = h;
    d_Wlo[i] = __float2bfloat16(v - __bfloat162float(h));
}

// ---------------------------------------------------------------------------
// Main HMMA GEMM with in-kernel x convert (unchanged from R10).
// ---------------------------------------------------------------------------
#define AST    144
#define ABYTES (192 * 144)
#define XFST   272
#define XF32B  (128 * XFST)
#define STG    (2 * ABYTES + XF32B)
#define XTST   272
#define XTILE  (64 * XTST)
#define XH_OFF 0
#define XL_OFF XTILE
#define STG0   (2 * XTILE)
#define SMEM_MAIN (STG0 + 2 * STG)

__global__ void __launch_bounds__(256, 1) cqt_mma(const float* __restrict__ x,
                                                  float* __restrict__ out) {
    extern __shared__ __align__(128) char dsm[];
    const unsigned sb = smem_u32(dsm);
    const int tid  = threadIdx.x;
    const int lane = tid & 31;
    const int wid  = tid >> 5;
    const int ms   = wid >> 1;
    const int nh   = wid & 1;
    const int f0   = blockIdx.x * 128;

    float acc[3][8][4];
    #pragma unroll
    for (int t = 0; t < 3; t++)
        #pragma unroll
        for (int nn = 0; nn < 8; nn++)
            #pragma unroll
            for (int j = 0; j < 4; j++) acc[t][nn][j] = 0.f;

    auto stage = [&](int kc, int b) {
        const unsigned sbuf = sb + STG0 + b * STG;
        const char* whi = (const char*)d_Whi + (size_t)kc * ABYTES;
        const char* wlo = (const char*)d_Wlo + (size_t)kc * ABYTES;
        for (int i = tid; i < ABYTES / 16; i += 256) {
            CPA(sbuf + i * 16, whi + i * 16);
            CPA(sbuf + ABYTES + i * 16, wlo + i * 16);
        }
        const unsigned xf = sbuf + 2 * ABYTES;
        for (int i = tid; i < 2048; i += 256) {
            const int f = i >> 4, seg = i & 15;
            const long gi = (long)(f0 + f) * HOP + kc * 64 + seg * 4;
            const long rem = (long)T_SAMPLES - gi;
            const int nb = rem >= 4 ? 16 : (rem > 0 ? (int)rem * 4 : 0);
            CPA_Z(xf + f * XFST + seg * 16, x + gi, nb);
        }
        CPCOMMIT();
    };

    stage(0, 0);
    stage(1, 1);

    for (int kc = 0; kc < 32; kc++) {
        const int b = kc & 1;
        CPWAIT1();
        __syncthreads();

        {
            const float* xfp = (const float*)(dsm + STG0 + b * STG + 2 * ABYTES);
            const int kk  = tid & 63;
            const int oct = tid >> 6;
            #pragma unroll
            for (int g = 0; g < 4; g++) {
                unsigned h[4], l[4];
                #pragma unroll
                for (int p = 0; p < 4; p++) {
                    const int f = oct * 32 + g * 8 + p * 2;
                    bsplit2(xfp[f * 68 + kk], xfp[(f + 1) * 68 + kk], h[p], l[p]);
                }
                const int fo = oct * 32 + g * 8;
                *(uint4*)(dsm + XH_OFF + kk * XTST + fo * 2) =
                    make_uint4(h[0], h[1], h[2], h[3]);
                *(uint4*)(dsm + XL_OFF + kk * XTST + fo * 2) =
                    make_uint4(l[0], l[1], l[2], l[3]);
            }
        }
        __syncthreads();

        const unsigned abhi = sb + STG0 + b * STG + ms * (48 * AST);
        const unsigned ablo = abhi + ABYTES;
        const unsigned xh = sb + XH_OFF + nh * 128;
        const unsigned xl = sb + XL_OFF + nh * 128;
        #pragma unroll
        for (int k16 = 0; k16 < 4; k16++) {
            const unsigned arow = (lane & 15) * AST + (lane >> 4) * 16 + k16 * 32;
            unsigned ahi[3][4], alo[3][4];
            LDSM4(ahi[0], abhi + arow);
            LDSM4(ahi[1], abhi + arow + 16 * AST);
            LDSM4(ahi[2], abhi + arow + 32 * AST);
            LDSM4(alo[0], ablo + arow);
            LDSM4(alo[1], ablo + arow + 16 * AST);
            LDSM4(alo[2], ablo + arow + 32 * AST);
            const unsigned xrow = (unsigned)((k16 * 16 + (lane & 15)) * XTST)
                                + (lane >> 4) * 16;
            unsigned bh[4][4], bl[4][4];
            #pragma unroll
            for (int g = 0; g < 4; g++) LDSM4T(bh[g], xh + xrow + g * 32);
            #pragma unroll
            for (int g = 0; g < 4; g++) LDSM4T(bl[g], xl + xrow + g * 32);
            #pragma unroll
            for (int t = 0; t < 3; t++) {
                #pragma unroll
                for (int g = 0; g < 4; g++) {
                    mma16816(acc[t][2 * g],     ahi[t], bh[g][0], bh[g][1]);
                    mma16816(acc[t][2 * g + 1], ahi[t], bh[g][2], bh[g][3]);
                    mma16816(acc[t][2 * g],     alo[t], bh[g][0], bh[g][1]);
                    mma16816(acc[t][2 * g + 1], alo[t], bh[g][2], bh[g][3]);
                    mma16816(acc[t][2 * g],     ahi[t], bl[g][0], bl[g][1]);
                    mma16816(acc[t][2 * g + 1], ahi[t], bl[g][2], bl[g][3]);
                }
            }
        }
        __syncthreads();
        if (kc + 2 < 32) stage(kc + 2, b);
    }

    __syncthreads();
    float* sI = (float*)dsm;
    if (ms >= 2) {
        #pragma unroll
        for (int t = 0; t < 3; t++)
            #pragma unroll
            for (int nn = 0; nn < 8; nn++) {
                const int mi = (ms - 2) * 48 + t * 16 + (lane >> 2);
                const int nl = nh * 64 + nn * 8 + 2 * (lane & 3);
                sI[mi * 132 + nl]           = acc[t][nn][0];
                sI[mi * 132 + nl + 1]       = acc[t][nn][1];
                sI[(mi + 8) * 132 + nl]     = acc[t][nn][2];
                sI[(mi + 8) * 132 + nl + 1] = acc[t][nn][3];
            }
    }
    __syncthreads();
    if (ms < 2) {
        #pragma unroll
        for (int t = 0; t < 3; t++)
            #pragma unroll
            for (int nn = 0; nn < 8; nn++) {
                const int m0 = ms * 48 + t * 16 + (lane >> 2);
                const int nl = nh * 64 + nn * 8 + 2 * (lane & 3);
                const int f  = f0 + nl;
                #pragma unroll
                for (int half = 0; half < 2; half++) {
                    const int m = m0 + half * 8;
                    if (m < NBINS) {
                        const float r0 = acc[t][nn][half * 2];
                        const float r1 = acc[t][nn][half * 2 + 1];
                        const float i0 = sI[m * 132 + nl];
                        const float i1 = sI[m * 132 + nl + 1];
                        if (f < NFRAMES)
                            out[m * NFRAMES + f] = sqrtf(r0 * r0 + i0 * i0);
                        if (f + 1 < NFRAMES)
                            out[m * NFRAMES + f + 1] = sqrtf(r1 * r1 + i1 * i1);
                    }
                }
            }
    }
}

extern "C" void kernel_launch(void* const* d_in, const int* in_sizes, int n_in,
                              void* d_out, int out_size) {
    const float* x    = (const float*)d_in[0];
    const float* wcos = (const float*)d_in[1];
    const float* wsin = (const float*)d_in[2];
    const float* kr   = (const float*)d_in[3];
    const float* ki   = (const float*)d_in[4];
    float* out = (float*)d_out;

    cudaFuncSetAttribute(cqt_pgemm, cudaFuncAttributeMaxDynamicSharedMemorySize,
                         SMEM_PG);
    cudaFuncSetAttribute(cqt_mma, cudaFuncAttributeMaxDynamicSharedMemorySize,
                         SMEM_MAIN);

    cqt_pgemm<<<dim3(64, 2), 256, SMEM_PG>>>(wcos, wsin, kr, ki);
    cqt_repack<<<(WELEMS + 255) / 256, 256>>>();
    cqt_mma<<<128, 256, SMEM_MAIN>>>(x, out);
}